// round 8
// baseline (speedup 1.0000x reference)
#include <cuda_runtime.h>

// FlowNetC correlation, specialized: B=4, C=128, H=W=96, PAD=20, K=1, MD=20, S1=1, S2=2
// out[b, iy*21+ix, y, x] = (1/128) * sum_c in1[b,c,y,x] * in2[b,c,y+dy,x+dx]
//
// R8: conflict-free LDS phases. Lane map cg=tid&7 (channel granule), xs=tid>>3:
// every 8-lane LDS phase shares x0 and spans cg=0..7 -> bank-group classes
// (row + cg) mod 8 all distinct (row stride RS=68 -> 17 granules, 17 ≡ 1 mod 8).
// 4 outputs/thread (x0+2*xi); j split into halves (acc <= 44 regs, no spill);
// 2 channel chunks of 64 staged to smem; half-1 visits chunks in order (c1,c0)
// so only 3 staging passes total. 63KB smem -> 3 CTAs/SM.

#define HW_ 9216            // 96*96 plane stride in floats
#define RS  68              // padded row stride for 64-ch chunk (floats)
#define S1F (96*RS)
#define S2ROWS 136          // x in [-20,115] -> row = x+20
#define S2F (S2ROWS*RS)
#define SMEM_BYTES ((S1F + S2F)*4)   // 63,104 B

__device__ __forceinline__ void stage_chunk(const float* __restrict__ in1,
                                            const float* __restrict__ in2,
                                            float* __restrict__ s1,
                                            float* __restrict__ s2,
                                            int b, int y, int y2, int cc, int tid)
{
    const float* g1 = in1 + ((size_t)(b * 128 + cc * 64) * 96 + y) * 96;
    #pragma unroll 1
    for (int i = tid; i < 96 * 16; i += 192) {
        int x = i % 96, g = i / 96;                 // g = float4 granule 0..15
        const float* p = g1 + g * 4 * HW_ + x;
        *(float4*)&s1[x * RS + g * 4] = make_float4(p[0], p[HW_], p[2*HW_], p[3*HW_]);
    }
    const float* g2 = in2 + ((size_t)(b * 128 + cc * 64) * 96 + y2) * 96;
    #pragma unroll 1
    for (int i = tid; i < 96 * 16; i += 192) {
        int x = i % 96, g = i / 96;
        const float* p = g2 + g * 4 * HW_ + x;
        *(float4*)&s2[(x + 20) * RS + g * 4] = make_float4(p[0], p[HW_], p[2*HW_], p[3*HW_]);
    }
}

// Accumulate one staged 64-channel chunk into acc[xi][jl], jl in [0,NJ), j = JLO+jl.
// Lane owns granules cg and cg+8. bv row for (xi, j) is x0 + 2*xi + 2*j = x0 + 2*(JLO+u),
// u = xi + jl in [0, NJ+2].
template<int NJ>
__device__ __forceinline__ void accum(const float* __restrict__ s1,
                                      const float* __restrict__ s2,
                                      int x0, int cg, int JLO, float (&acc)[4][NJ])
{
    #pragma unroll
    for (int k = 0; k < 2; k++) {
        const int cb = cg + k * 8;
        const float* p1 = s1 + x0 * RS + cb * 4;
        const float4 a0 = *(const float4*)(p1);
        const float4 a1 = *(const float4*)(p1 + 2 * RS);
        const float4 a2 = *(const float4*)(p1 + 4 * RS);
        const float4 a3 = *(const float4*)(p1 + 6 * RS);
        const float* p2 = s2 + (x0 + 2 * JLO) * RS + cb * 4;
        #pragma unroll
        for (int u = 0; u < NJ + 3; u++) {
            const float4 bv = *(const float4*)(p2 + 2 * u * RS);
            if (u < NJ) {
                float s = acc[0][u];
                s = fmaf(a0.x, bv.x, s); s = fmaf(a0.y, bv.y, s);
                s = fmaf(a0.z, bv.z, s); s = fmaf(a0.w, bv.w, s);
                acc[0][u] = s;
            }
            if (u >= 1 && u - 1 < NJ) {
                float s = acc[1][u - 1];
                s = fmaf(a1.x, bv.x, s); s = fmaf(a1.y, bv.y, s);
                s = fmaf(a1.z, bv.z, s); s = fmaf(a1.w, bv.w, s);
                acc[1][u - 1] = s;
            }
            if (u >= 2 && u - 2 < NJ) {
                float s = acc[2][u - 2];
                s = fmaf(a2.x, bv.x, s); s = fmaf(a2.y, bv.y, s);
                s = fmaf(a2.z, bv.z, s); s = fmaf(a2.w, bv.w, s);
                acc[2][u - 2] = s;
            }
            if (u >= 3 && u - 3 < NJ) {
                float s = acc[3][u - 3];
                s = fmaf(a3.x, bv.x, s); s = fmaf(a3.y, bv.y, s);
                s = fmaf(a3.z, bv.z, s); s = fmaf(a3.w, bv.w, s);
                acc[3][u - 3] = s;
            }
        }
    }
}

// Butterfly-reduce over the 8 cg lanes (phase-local: xor 1,2,4 stay in the group),
// then lane cg stores xi = cg&3, j parity = cg>>2.
template<int NJ>
__device__ __forceinline__ void reduce_store(float (&acc)[4][NJ], int JLO, int x0,
                                             int cg, float* __restrict__ out,
                                             size_t obase)
{
    const float inv = 1.0f / 128.0f;
    #pragma unroll
    for (int xi = 0; xi < 4; xi++)
        #pragma unroll
        for (int j = 0; j < NJ; j++) {
            float v = acc[xi][j];
            v += __shfl_xor_sync(0xffffffffu, v, 1);
            v += __shfl_xor_sync(0xffffffffu, v, 2);
            v += __shfl_xor_sync(0xffffffffu, v, 4);
            acc[xi][j] = v * inv;
        }
    const int myxi = cg & 3;
    const int par  = cg >> 2;
    float* o = out + obase + x0 + 2 * myxi;
    #pragma unroll
    for (int j = 0; j < NJ; j++)
        if ((j & 1) == par)
            o[(size_t)(JLO + j) * HW_] = acc[myxi][j];
}

__global__ __launch_bounds__(192, 3)
void corr_kernel(const float* __restrict__ in1, const float* __restrict__ in2,
                 float* __restrict__ out)
{
    extern __shared__ float smem[];
    float* s1 = smem;
    float* s2 = smem + S1F;

    const int tid   = threadIdx.x;
    const int y     = blockIdx.x;    // 0..95
    const int dyIdx = blockIdx.y;    // 0..20
    const int b     = blockIdx.z;    // 0..3

    const int y2 = y + (dyIdx - 10) * 2;
    const size_t obase = ((size_t)(b * 441 + dyIdx * 21) * 96 + y) * 96;

    if ((unsigned)y2 >= 96u) {
        // whole dy slab for this row is zeros
        for (int i = tid; i < 21 * 96; i += 192) {
            int j = i / 96, x = i - j * 96;
            out[obase + (size_t)j * HW_ + x] = 0.f;
        }
        return;
    }

    // zero halo rows of s2 once (x in [-20,-1] and [96,115]); never overwritten
    for (int i = tid; i < 40 * 16; i += 192) {
        int r = i % 40, g = i / 40;
        int row = (r < 20) ? r : (96 + r);        // rows 0..19, 116..135
        *(float4*)&s2[row * RS + g * 4] = make_float4(0.f, 0.f, 0.f, 0.f);
    }

    const int cg = tid & 7;                  // channel granule lane
    const int xs = tid >> 3;                 // 0..23
    const int x0 = 8 * (xs >> 1) + (xs & 1); // outputs x0+2*xi, xi=0..3, tile 0..95

    // ---- half A: j in [0,11) ----
    float accA[4][11];
    #pragma unroll
    for (int xi = 0; xi < 4; xi++)
        #pragma unroll
        for (int j = 0; j < 11; j++) accA[xi][j] = 0.f;

    stage_chunk(in1, in2, s1, s2, b, y, y2, 0, tid);
    __syncthreads();
    accum<11>(s1, s2, x0, cg, 0, accA);
    __syncthreads();
    stage_chunk(in1, in2, s1, s2, b, y, y2, 1, tid);
    __syncthreads();
    accum<11>(s1, s2, x0, cg, 0, accA);
    reduce_store<11>(accA, 0, x0, cg, out, obase);

    // ---- half B: j in [11,21); chunk 1 is still resident, do it first ----
    float accB[4][10];
    #pragma unroll
    for (int xi = 0; xi < 4; xi++)
        #pragma unroll
        for (int j = 0; j < 10; j++) accB[xi][j] = 0.f;

    accum<10>(s1, s2, x0, cg, 11, accB);
    __syncthreads();
    stage_chunk(in1, in2, s1, s2, b, y, y2, 0, tid);
    __syncthreads();
    accum<10>(s1, s2, x0, cg, 11, accB);
    reduce_store<10>(accB, 11, x0, cg, out, obase);
}

extern "C" void kernel_launch(void* const* d_in, const int* in_sizes, int n_in,
                              void* d_out, int out_size)
{
    const float* in1 = (const float*)d_in[0];
    const float* in2 = (const float*)d_in[1];
    float* out = (float*)d_out;

    cudaFuncSetAttribute(corr_kernel, cudaFuncAttributeMaxDynamicSharedMemorySize, SMEM_BYTES);

    dim3 grid(96, 21, 4);   // y, dy, batch
    corr_kernel<<<grid, 192, SMEM_BYTES>>>(in1, in2, out);
}

// round 9
// speedup vs baseline: 1.1297x; 1.1297x over previous
#include <cuda_runtime.h>

// FlowNetC correlation, specialized: B=4, C=128, H=W=96, PAD=20, K=1, MD=20, S1=1, S2=2
// out[b, iy*21+ix, y, x] = (1/128) * sum_c in1[b,c,y,x] * in2[b,c,y+dy,x+dx]
//
// R9 = R7 (308us) with ONE change: the xs -> x0 map. R7 put phase-mate lanes at
// x0 diff 1 -> LDS bank-group classes {x0+cg} overlapped on 3 of 8 banks (2-way
// conflict on every compute LDS). New map: s=(xs>=24), q=xs-24s, x0=4q+s ->
// phase-mates differ by 4 mod 8 -> classes {0..3} vs {4..7}: conflict-free.
// Coverage unchanged: {4q+s} u {4q+s+2} tiles 0..95.

#define HW_ 9216            // 96*96 plane stride in floats
#define RS  68              // padded row stride for 64-ch chunk (floats)
#define S1F (96*RS)         // 6528
#define S2ROWS 136          // x in [-20,115] -> row = x+20
#define S2F (S2ROWS*RS)     // 9248
#define SMEM_FLOATS (S1F + S2F)
#define SMEM_BYTES  (SMEM_FLOATS*4)   // 63,104 B

__global__ __launch_bounds__(192, 3)
void corr_kernel(const float* __restrict__ in1, const float* __restrict__ in2,
                 float* __restrict__ out)
{
    extern __shared__ float smem[];
    float* s1 = smem;
    float* s2 = smem + S1F;

    const int tid   = threadIdx.x;
    const int y     = blockIdx.x;    // 0..95
    const int dyIdx = blockIdx.y;    // 0..20
    const int b     = blockIdx.z;    // 0..3

    const int  y2       = y + (dyIdx - 10) * 2;
    const bool rowValid = ((unsigned)y2 < 96u);

    const size_t obase = ((size_t)(b * 441 + dyIdx * 21) * 96 + y) * 96;

    if (!rowValid) {
        // whole dy slab for this row is zeros (block-uniform; no syncs touched)
        for (int i = tid; i < 21 * 96; i += 192) {
            int j = i / 96, x = i - j * 96;
            out[obase + (size_t)j * HW_ + x] = 0.f;
        }
        return;
    }

    const int cg = tid & 3;                  // channel-group lane (shfl-reduced)
    const int xs = tid >> 2;                 // 0..47
    const int s  = (xs >= 24) ? 1 : 0;       // odd/even x family (warp-uniform)
    const int q  = xs - 24 * s;              // 0..23
    const int x0 = 4 * q + s;                // outputs (x0, x0+2); phase-mates differ by 4
    const int x1 = x0 + 2;

    float acc0[21], acc1[21];
    #pragma unroll
    for (int j = 0; j < 21; j++) { acc0[j] = 0.f; acc1[j] = 0.f; }

    #pragma unroll 1
    for (int cc = 0; cc < 2; cc++) {
        // ---- stage in1 row y, channels [cc*64, cc*64+64) : layout [x][c] ----
        const float* g1 = in1 + ((size_t)(b * 128 + cc * 64) * 96 + y) * 96;
        for (int i = tid; i < 96 * 16; i += 192) {
            int x = i % 96, g = i / 96;                      // g = float4 granule 0..15
            const float* p = g1 + g * 4 * HW_ + x;
            *(float4*)&s1[x * RS + g * 4] =
                make_float4(p[0], p[HW_], p[2 * HW_], p[3 * HW_]);
        }
        // ---- zero halo rows (x in [-20,-1] and [96,115]) ----
        for (int i = tid; i < 40 * 16; i += 192) {
            int r = i % 40, g = i / 40;
            int row = (r < 20) ? r : (96 + r);               // rows 0..19, 116..135
            *(float4*)&s2[row * RS + g * 4] = make_float4(0.f, 0.f, 0.f, 0.f);
        }
        // ---- stage in2 row y2, same channel chunk ----
        const float* g2 = in2 + ((size_t)(b * 128 + cc * 64) * 96 + y2) * 96;
        for (int i = tid; i < 96 * 16; i += 192) {
            int x = i % 96, g = i / 96;
            const float* p = g2 + g * 4 * HW_ + x;
            *(float4*)&s2[(x + 20) * RS + g * 4] =
                make_float4(p[0], p[HW_], p[2 * HW_], p[3 * HW_]);
        }
        __syncthreads();

        // ---- compute: lane cg owns granules k*4+cg, k=0..3 (16 ch per chunk) ----
        #pragma unroll 1
        for (int k = 0; k < 4; k++) {
            const int cb = k * 4 + cg;                       // granule 0..15
            const float4 a0 = *(const float4*)&s1[x0 * RS + cb * 4];
            const float4 a1 = *(const float4*)&s1[x1 * RS + cb * 4];
            const float* p2 = &s2[x0 * RS + cb * 4];
            // sliding window: s2 row x0+2t feeds acc0[t] (t<21) and acc1[t-1] (t>0)
            #pragma unroll
            for (int t = 0; t <= 21; t++) {
                const float4 bv = *(const float4*)(p2 + 2 * t * RS);
                if (t < 21) {
                    float v = acc0[t];
                    v = fmaf(a0.x, bv.x, v); v = fmaf(a0.y, bv.y, v);
                    v = fmaf(a0.z, bv.z, v); v = fmaf(a0.w, bv.w, v);
                    acc0[t] = v;
                }
                if (t > 0) {
                    float v = acc1[t - 1];
                    v = fmaf(a1.x, bv.x, v); v = fmaf(a1.y, bv.y, v);
                    v = fmaf(a1.z, bv.z, v); v = fmaf(a1.w, bv.w, v);
                    acc1[t - 1] = v;
                }
            }
        }
        __syncthreads();   // before chunk 1 overwrites smem
    }

    // ---- reduce the 4 channel-group partials (lanes 4*xs + cg) ----
    const float inv = 1.0f / 128.0f;
    #pragma unroll
    for (int j = 0; j < 21; j++) {
        float v0 = acc0[j];
        v0 += __shfl_xor_sync(0xffffffffu, v0, 1);
        v0 += __shfl_xor_sync(0xffffffffu, v0, 2);
        float v1 = acc1[j];
        v1 += __shfl_xor_sync(0xffffffffu, v1, 1);
        v1 += __shfl_xor_sync(0xffffffffu, v1, 2);
        acc0[j] = v0 * inv;
        acc1[j] = v1 * inv;
    }
    if (cg == 0) {
        #pragma unroll
        for (int j = 0; j < 21; j++)
            out[obase + (size_t)j * HW_ + x0] = acc0[j];
    } else if (cg == 1) {
        #pragma unroll
        for (int j = 0; j < 21; j++)
            out[obase + (size_t)j * HW_ + x1] = acc1[j];
    }
}

extern "C" void kernel_launch(void* const* d_in, const int* in_sizes, int n_in,
                              void* d_out, int out_size)
{
    const float* in1 = (const float*)d_in[0];
    const float* in2 = (const float*)d_in[1];
    float* out = (float*)d_out;

    cudaFuncSetAttribute(corr_kernel, cudaFuncAttributeMaxDynamicSharedMemorySize, SMEM_BYTES);

    dim3 grid(96, 21, 4);   // y, dy, batch
    corr_kernel<<<grid, 192, SMEM_BYTES>>>(in1, in2, out);
}